// round 10
// baseline (speedup 1.0000x reference)
#include <cuda_runtime.h>
#include <cuda_fp16.h>

// ---------------------------------------------------------------------------
// DummyGAT: h = x@W; GAT edge softmax + aggregation; out = mean(relu(agg)@W_lin + b_lin)
// N = 100000 nodes, E = 1.6M edges, IN=128, HID=64, OUT=64
// 4 launches: [gemm+hist] -> [lookback scan] -> [scatter] -> [agg+final]
// agg: batch-4 gather per 16-lane half (≈16 L2 chains/warp), spread reduction.
// ---------------------------------------------------------------------------

#define N_MAX 100000
#define E_MAX 1600000
#define SCAN_BLOCKS 391   // ceil(100000/256)

__device__ __align__(256) __half g_h2[N_MAX * 64];    // h in fp16 (gather operand)
__device__ __align__(256) float  g_asrc[N_MAX];
__device__ __align__(256) float  g_adst[N_MAX];
__device__ __align__(256) int    g_deg[N_MAX];        // in-degree (zeroed by agg)
__device__ __align__(256) int    g_start[N_MAX];      // CSR row start (from scan)
__device__ __align__(256) int    g_cursor[N_MAX];     // scatter cursor
__device__ __align__(256) int    g_csrc[E_MAX];       // CSR: src per (dst-sorted) edge
__device__ __align__(256) unsigned long long g_pkt[SCAN_BLOCKS]; // lookback, zeroed by scatter
__device__ __align__(256) float  g_smulti[64 * 64];   // 64-way-spread node-sum slots (zeroed by agg)
__device__ int g_done;                                // zeroed by agg

__device__ __forceinline__ float lrelu(float x) { return x > 0.f ? x : 0.2f * x; }

// ---------------------------------------------------------------------------
// Kernel 1: blocks [0,GB): h = x@W + attention scores (k-major x tile -> FFMA-bound).
// blocks [GB,..): in-degree histogram (overlaps under the gemm blocks).
// ---------------------------------------------------------------------------
__global__ void gemm_hist_kernel(const float* __restrict__ x, const float* __restrict__ W,
                                 const float* __restrict__ att_src, const float* __restrict__ att_dst,
                                 const int* __restrict__ ei, int N, int E, int GB) {
    if (blockIdx.x >= GB) {               // ---- histogram part ----
        int i = (blockIdx.x - GB) * 256 + threadIdx.x;
        if (i < E) atomicAdd(&g_deg[ei[E + i]], 1);
        return;
    }
    // ---- gemm part ----
    int row0 = blockIdx.x * 64;

    __shared__ float xs[64 * 68];    // k-major: xs[k*68 + r]
    __shared__ float ws[64 * 64];    // [k][c]
    int tx = threadIdx.x & 15;       // col group (4 cols)
    int ty = threadIdx.x >> 4;       // row group (4 rows)
    float acc[4][4] = {};

    for (int k0 = 0; k0 < 128; k0 += 64) {
        #pragma unroll
        for (int i = 0; i < 4; i++) {
            int idx = threadIdx.x + i * 256;
            int r = idx >> 4, c4 = idx & 15;
            int grow = row0 + r;
            float4 v = make_float4(0.f, 0.f, 0.f, 0.f);
            if (grow < N) v = ((const float4*)x)[grow * 32 + (k0 >> 2) + c4];
            int kk = c4 * 4;
            xs[(kk + 0) * 68 + r] = v.x;
            xs[(kk + 1) * 68 + r] = v.y;
            xs[(kk + 2) * 68 + r] = v.z;
            xs[(kk + 3) * 68 + r] = v.w;
        }
        #pragma unroll
        for (int i = 0; i < 4; i++) {
            int idx = threadIdx.x + i * 256;
            ((float4*)ws)[idx] = ((const float4*)(W + k0 * 64))[idx];
        }
        __syncthreads();

        #pragma unroll 16
        for (int k = 0; k < 64; k++) {
            float4 xv = *(float4*)&xs[k * 68 + ty * 4];   // broadcast: 2 addrs/warp
            float4 wv = *(float4*)&ws[k * 64 + tx * 4];
            acc[0][0] += xv.x * wv.x; acc[0][1] += xv.x * wv.y; acc[0][2] += xv.x * wv.z; acc[0][3] += xv.x * wv.w;
            acc[1][0] += xv.y * wv.x; acc[1][1] += xv.y * wv.y; acc[1][2] += xv.y * wv.z; acc[1][3] += xv.y * wv.w;
            acc[2][0] += xv.z * wv.x; acc[2][1] += xv.z * wv.y; acc[2][2] += xv.z * wv.z; acc[2][3] += xv.z * wv.w;
            acc[3][0] += xv.w * wv.x; acc[3][1] += xv.w * wv.y; acc[3][2] += xv.w * wv.z; acc[3][3] += xv.w * wv.w;
        }
        __syncthreads();
    }

    // attention scores via width-16 shuffle reduce
    float4 as4 = ((const float4*)att_src)[tx];
    float4 ad4 = ((const float4*)att_dst)[tx];
    #pragma unroll
    for (int i = 0; i < 4; i++) {
        float pa = acc[i][0] * as4.x + acc[i][1] * as4.y + acc[i][2] * as4.z + acc[i][3] * as4.w;
        float pd = acc[i][0] * ad4.x + acc[i][1] * ad4.y + acc[i][2] * ad4.z + acc[i][3] * ad4.w;
        #pragma unroll
        for (int off = 8; off; off >>= 1) {
            pa += __shfl_down_sync(0xffffffffu, pa, off, 16);
            pd += __shfl_down_sync(0xffffffffu, pd, off, 16);
        }
        if (tx == 0) {
            int r = row0 + ty * 4 + i;
            if (r < N) { g_asrc[r] = pa; g_adst[r] = pd; }
        }
    }

    #pragma unroll
    for (int i = 0; i < 4; i++) {
        int r = row0 + ty * 4 + i;
        if (r >= N) continue;
        union { __half2 h[2]; float2 f; } u;
        u.h[0] = __floats2half2_rn(acc[i][0], acc[i][1]);
        u.h[1] = __floats2half2_rn(acc[i][2], acc[i][3]);
        ((float2*)g_h2)[r * 16 + tx] = u.f;
    }
}

// ---------------------------------------------------------------------------
// Kernel 2: single-pass exclusive scan of g_deg -> g_start & g_cursor
// (decoupled lookback; all 391 blocks co-resident in one wave).
// ---------------------------------------------------------------------------
#define FLAG_AGG  (1ull << 32)
#define FLAG_INCL (2ull << 32)

__global__ void scan_kernel(int N) {
    int t = threadIdx.x;
    int bid = blockIdx.x;
    int g = bid * 256 + t;
    int lane = t & 31, w = t >> 5;
    int v = (g < N) ? g_deg[g] : 0;
    int incl = v;
    #pragma unroll
    for (int off = 1; off < 32; off <<= 1) {
        int nv = __shfl_up_sync(0xffffffffu, incl, off);
        if (lane >= off) incl += nv;
    }
    __shared__ int wsum[8];
    if (lane == 31) wsum[w] = incl;
    __syncthreads();
    if (t < 8) {
        int xw = wsum[t];
        int in2 = xw;
        #pragma unroll
        for (int off = 1; off < 8; off <<= 1) {
            int nv = __shfl_up_sync(0xffu, in2, off);
            if (t >= off) in2 += nv;
        }
        wsum[t] = in2 - xw;   // exclusive warp offsets
    }
    __syncthreads();
    int excl = incl - v + wsum[w];

    __shared__ int sPrefix;
    __shared__ int sTotal;
    if (t == 255) sTotal = excl + v;
    __syncthreads();
    if (t == 0) {
        unsigned long long total = (unsigned long long)(unsigned)sTotal;
        if (bid == 0) {
            atomicExch(&g_pkt[0], total | FLAG_INCL);
            sPrefix = 0;
        } else {
            atomicExch(&g_pkt[bid], total | FLAG_AGG);
            long long run = 0;
            int j = bid - 1;
            while (true) {
                unsigned long long p;
                do { p = atomicAdd(&g_pkt[j], 0ull); } while ((p >> 32) == 0);
                run += (unsigned)(p & 0xffffffffu);
                if (p & FLAG_INCL) break;
                j--;
            }
            atomicExch(&g_pkt[bid], (total + (unsigned long long)(unsigned)run) | FLAG_INCL);
            sPrefix = (int)run;
        }
    }
    __syncthreads();
    if (g < N) {
        int st = excl + sPrefix;
        g_start[g] = st;
        g_cursor[g] = st;
    }
}

// ---------------------------------------------------------------------------
// Kernel 3: scatter edges into CSR; re-zeroes g_pkt for the next replay.
// ---------------------------------------------------------------------------
__global__ void scatter_kernel(const int* __restrict__ ei, int E) {
    int i = blockIdx.x * blockDim.x + threadIdx.x;
    if (i < SCAN_BLOCKS) g_pkt[i] = 0ull;
    if (i >= E) return;
    int s = ei[i];
    int d = ei[E + i];
    int pos = atomicAdd(&g_cursor[d], 1);
    g_csrc[pos] = s;
}

// ---------------------------------------------------------------------------
// Kernel 4: warp-per-node gather aggregation, batch-4 per 16-lane half.
// Each batch iteration issues 4 independent index loads, 4 independent
// a_src loads, 4 independent 128B row loads -> ~16 L2 chains per warp.
// Block partials red into 64-way-spread slots; last-done block does the
// final 64x64 matvec and re-zeroes all state for graph replay.
// ---------------------------------------------------------------------------
__global__ void agg_kernel(const float* __restrict__ bias,
                           const float* __restrict__ W_lin, const float* __restrict__ b_lin,
                           float* __restrict__ out, float invN, int N) {
    __shared__ float sm[64];
    __shared__ float sf[64];
    __shared__ int lastFlag;
    int t = threadIdx.x;
    if (t < 64) sm[t] = 0.f;
    __syncthreads();

    int wid = t >> 5, lane = t & 31;
    int half = lane >> 4, l16 = lane & 15;
    int node = blockIdx.x * 8 + wid;

    if (node < N) {
        int deg = g_deg[node];
        int start = g_start[node];
        if (lane == 0) g_deg[node] = 0;        // cleanup for next replay's histogram
        float adst_n = g_adst[node];
        float asrc_n = g_asrc[node];
        float4 acc = make_float4(0.f, 0.f, 0.f, 0.f);
        float dsum = 0.f;

        // self loop (half 0 accumulates the feature part)
        float e_self = __expf(lrelu(asrc_n + adst_n));
        if (half == 0) {
            float2 p = __ldg((const float2*)g_h2 + node * 16 + l16);
            float2 lo = __half22float2(((const __half2*)&p)[0]);
            float2 hi = __half22float2(((const __half2*)&p)[1]);
            acc.x = lo.x * e_self; acc.y = lo.y * e_self;
            acc.z = hi.x * e_self; acc.w = hi.y * e_self;
        }

        // this half owns edges k = half, half+2, ...; batch 4 per iteration
        const int* row = g_csrc + start;
        for (int k = half; k < deg; k += 8) {
            bool v0 = true;               // k < deg by loop condition
            bool v1 = (k + 2) < deg;
            bool v2 = (k + 4) < deg;
            bool v3 = (k + 6) < deg;
            int s0 = __ldg(row + k);
            int s1 = v1 ? __ldg(row + k + 2) : 0;
            int s2 = v2 ? __ldg(row + k + 4) : 0;
            int s3 = v3 ? __ldg(row + k + 6) : 0;
            float a0 = __ldg(g_asrc + s0);
            float a1 = v1 ? __ldg(g_asrc + s1) : 0.f;
            float a2 = v2 ? __ldg(g_asrc + s2) : 0.f;
            float a3 = v3 ? __ldg(g_asrc + s3) : 0.f;
            float2 p0 = __ldg((const float2*)g_h2 + s0 * 16 + l16);
            float2 p1 = v1 ? __ldg((const float2*)g_h2 + s1 * 16 + l16) : make_float2(0.f, 0.f);
            float2 p2 = v2 ? __ldg((const float2*)g_h2 + s2 * 16 + l16) : make_float2(0.f, 0.f);
            float2 p3 = v3 ? __ldg((const float2*)g_h2 + s3 * 16 + l16) : make_float2(0.f, 0.f);

            float e0 = __expf(lrelu(a0 + adst_n));
            float e1 = v1 ? __expf(lrelu(a1 + adst_n)) : 0.f;
            float e2 = v2 ? __expf(lrelu(a2 + adst_n)) : 0.f;
            float e3 = v3 ? __expf(lrelu(a3 + adst_n)) : 0.f;
            dsum += (e0 + e1) + (e2 + e3);

            float2 lo, hi;
            lo = __half22float2(((const __half2*)&p0)[0]); hi = __half22float2(((const __half2*)&p0)[1]);
            acc.x += lo.x * e0; acc.y += lo.y * e0; acc.z += hi.x * e0; acc.w += hi.y * e0;
            lo = __half22float2(((const __half2*)&p1)[0]); hi = __half22float2(((const __half2*)&p1)[1]);
            acc.x += lo.x * e1; acc.y += lo.y * e1; acc.z += hi.x * e1; acc.w += hi.y * e1;
            lo = __half22float2(((const __half2*)&p2)[0]); hi = __half22float2(((const __half2*)&p2)[1]);
            acc.x += lo.x * e2; acc.y += lo.y * e2; acc.z += hi.x * e2; acc.w += hi.y * e2;
            lo = __half22float2(((const __half2*)&p3)[0]); hi = __half22float2(((const __half2*)&p3)[1]);
            acc.x += lo.x * e3; acc.y += lo.y * e3; acc.z += hi.x * e3; acc.w += hi.y * e3;
        }

        // combine the two halves (lane l and l^16 hold the same columns)
        float dother = __shfl_xor_sync(0xffffffffu, dsum, 16);
        float denom = dsum + dother + e_self;
        acc.x += __shfl_xor_sync(0xffffffffu, acc.x, 16);
        acc.y += __shfl_xor_sync(0xffffffffu, acc.y, 16);
        acc.z += __shfl_xor_sync(0xffffffffu, acc.z, 16);
        acc.w += __shfl_xor_sync(0xffffffffu, acc.w, 16);

        if (half == 0) {
            float inv = 1.f / denom;
            float4 bv = ((const float4*)bias)[l16];
            atomicAdd(&sm[l16 * 4 + 0], fmaxf(acc.x * inv + bv.x, 0.f));
            atomicAdd(&sm[l16 * 4 + 1], fmaxf(acc.y * inv + bv.y, 0.f));
            atomicAdd(&sm[l16 * 4 + 2], fmaxf(acc.z * inv + bv.z, 0.f));
            atomicAdd(&sm[l16 * 4 + 3], fmaxf(acc.w * inv + bv.w, 0.f));
        }
    }
    __syncthreads();
    if (t < 16) {
        float4 v = *(float4*)&sm[t * 4];
        float* dst = g_smulti + (blockIdx.x & 63) * 64 + t * 4;   // 64-way spread
        asm volatile("red.global.add.v4.f32 [%0], {%1,%2,%3,%4};"
                     :: "l"(dst), "f"(v.x), "f"(v.y), "f"(v.z), "f"(v.w)
                     : "memory");
        __threadfence();
    }
    __syncthreads();
    if (t == 0) {
        int old = atomicAdd(&g_done, 1);
        lastFlag = (old == (int)gridDim.x - 1);
    }
    __syncthreads();

    if (lastFlag) {
        __threadfence();   // acquire: all blocks' reds visible
        if (t < 64) {
            float v = 0.f;
            #pragma unroll 8
            for (int j = 0; j < 64; j++) {
                float pj;
                asm volatile("ld.global.cg.f32 %0, [%1];" : "=f"(pj) : "l"(g_smulti + j * 64 + t));
                v += pj;
                g_smulti[j * 64 + t] = 0.f;   // cleanup for next replay
            }
            sf[t] = v;
        }
        __syncthreads();
        if (t < 64) {
            float acc2 = b_lin[t];
            #pragma unroll 8
            for (int c = 0; c < 64; c++)
                acc2 += (sf[c] * invN) * W_lin[c * 64 + t];
            out[t] = acc2;
        }
        if (t == 0) g_done = 0;               // cleanup for next replay
    }
}

// ---------------------------------------------------------------------------
extern "C" void kernel_launch(void* const* d_in, const int* in_sizes, int n_in,
                              void* d_out, int out_size) {
    const float* x       = (const float*)d_in[0];
    const int*   ei      = (const int*)d_in[1];
    const float* W       = (const float*)d_in[2];
    const float* att_src = (const float*)d_in[3];
    const float* att_dst = (const float*)d_in[4];
    const float* bias    = (const float*)d_in[5];
    const float* W_lin   = (const float*)d_in[6];
    const float* b_lin   = (const float*)d_in[7];

    int N = in_sizes[0] / 128;   // 100000
    int E = in_sizes[1] / 2;     // 1600000
    int GB = (N + 63) / 64;      // gemm blocks
    int HB = (E + 255) / 256;    // hist blocks

    gemm_hist_kernel<<<GB + HB, 256>>>(x, W, att_src, att_dst, ei, N, E, GB);
    scan_kernel<<<(N + 255) / 256, 256>>>(N);
    scatter_kernel<<<(E + 255) / 256, 256>>>(ei, E);
    agg_kernel<<<(N + 7) / 8, 256>>>(bias, W_lin, b_lin, (float*)d_out, 1.0f / (float)N, N);
}

// round 11
// speedup vs baseline: 1.3389x; 1.3389x over previous
#include <cuda_runtime.h>
#include <cuda_fp16.h>

// ---------------------------------------------------------------------------
// DummyGAT: h = x@W; GAT edge softmax + aggregation; out = mean(relu(agg)@W_lin + b_lin)
// N = 100000 nodes, E = 1.6M edges, IN=128, HID=64, OUT=64
// 5 launches: [gemm+hist+zero] -> [scan] -> [scatter] -> [edge partials] -> [finish]
// Aggregation is EDGE-PARALLEL (O(1) loads/thread, in-block run dedup, few REDs):
// throughput-bound by construction, immune to latency-mode environment variance.
// ---------------------------------------------------------------------------

#define N_MAX 100000
#define E_MAX 1600000
#define SCAN_BLOCKS 391   // ceil(100000/256)

__device__ __align__(256) __half g_h2[N_MAX * 64];    // h in fp16 (gather operand)
__device__ __align__(256) float  g_asrc[N_MAX];
__device__ __align__(256) float  g_adst[N_MAX];
__device__ __align__(256) float  g_agg[N_MAX * 64];   // edge-sum accumulator (zeroed in K1)
__device__ __align__(256) float  g_denom[N_MAX];      // edge exp-sum (zeroed in K1)
__device__ __align__(256) int    g_deg[N_MAX];        // in-degree (zeroed by finish)
__device__ __align__(256) int    g_cursor[N_MAX];     // scan result / scatter cursor
__device__ __align__(256) int    g_csrc[E_MAX];       // CSR: src per (dst-sorted) slot
__device__ __align__(256) int    g_cdst[E_MAX];       // CSR: dst per slot
__device__ __align__(256) unsigned long long g_pkt[SCAN_BLOCKS]; // lookback, zeroed by scatter
__device__ __align__(256) float  g_smulti[64 * 64];   // spread node-sum slots (zeroed by finish)
__device__ int g_done;                                // zeroed by finish

__device__ __forceinline__ float lrelu(float x) { return x > 0.f ? x : 0.2f * x; }

// ---------------------------------------------------------------------------
// Kernel 1: three block partitions.
//  [0,GB): h = x@W + attention scores (k-major x tile -> FFMA-bound)
//  [GB,GB+HB): in-degree histogram
//  [GB+HB,..): zero g_agg and g_denom (float4 streams, hidden under gemm)
// ---------------------------------------------------------------------------
__global__ void gemm_hist_zero_kernel(const float* __restrict__ x, const float* __restrict__ W,
                                      const float* __restrict__ att_src, const float* __restrict__ att_dst,
                                      const int* __restrict__ ei, int N, int E, int GB, int HB) {
    if (blockIdx.x >= GB + HB) {          // ---- zero partition ----
        int i = (blockIdx.x - GB - HB) * 256 + threadIdx.x;
        int nAgg = N * 16;                // g_agg in float4 units
        if (i < nAgg) ((float4*)g_agg)[i] = make_float4(0.f, 0.f, 0.f, 0.f);
        else if (i - nAgg < N / 4) ((float4*)g_denom)[i - nAgg] = make_float4(0.f, 0.f, 0.f, 0.f);
        return;
    }
    if (blockIdx.x >= GB) {               // ---- histogram partition ----
        int i = (blockIdx.x - GB) * 256 + threadIdx.x;
        if (i < E) atomicAdd(&g_deg[ei[E + i]], 1);
        return;
    }
    // ---- gemm partition ----
    int row0 = blockIdx.x * 64;

    __shared__ float xs[64 * 68];    // k-major: xs[k*68 + r]
    __shared__ float ws[64 * 64];    // [k][c]
    int tx = threadIdx.x & 15;       // col group (4 cols)
    int ty = threadIdx.x >> 4;       // row group (4 rows)
    float acc[4][4] = {};

    for (int k0 = 0; k0 < 128; k0 += 64) {
        #pragma unroll
        for (int i = 0; i < 4; i++) {
            int idx = threadIdx.x + i * 256;
            int r = idx >> 4, c4 = idx & 15;
            int grow = row0 + r;
            float4 v = make_float4(0.f, 0.f, 0.f, 0.f);
            if (grow < N) v = ((const float4*)x)[grow * 32 + (k0 >> 2) + c4];
            int kk = c4 * 4;
            xs[(kk + 0) * 68 + r] = v.x;
            xs[(kk + 1) * 68 + r] = v.y;
            xs[(kk + 2) * 68 + r] = v.z;
            xs[(kk + 3) * 68 + r] = v.w;
        }
        #pragma unroll
        for (int i = 0; i < 4; i++) {
            int idx = threadIdx.x + i * 256;
            ((float4*)ws)[idx] = ((const float4*)(W + k0 * 64))[idx];
        }
        __syncthreads();

        #pragma unroll 16
        for (int k = 0; k < 64; k++) {
            float4 xv = *(float4*)&xs[k * 68 + ty * 4];   // broadcast: 2 addrs/warp
            float4 wv = *(float4*)&ws[k * 64 + tx * 4];
            acc[0][0] += xv.x * wv.x; acc[0][1] += xv.x * wv.y; acc[0][2] += xv.x * wv.z; acc[0][3] += xv.x * wv.w;
            acc[1][0] += xv.y * wv.x; acc[1][1] += xv.y * wv.y; acc[1][2] += xv.y * wv.z; acc[1][3] += xv.y * wv.w;
            acc[2][0] += xv.z * wv.x; acc[2][1] += xv.z * wv.y; acc[2][2] += xv.z * wv.z; acc[2][3] += xv.z * wv.w;
            acc[3][0] += xv.w * wv.x; acc[3][1] += xv.w * wv.y; acc[3][2] += xv.w * wv.z; acc[3][3] += xv.w * wv.w;
        }
        __syncthreads();
    }

    // attention scores via width-16 shuffle reduce
    float4 as4 = ((const float4*)att_src)[tx];
    float4 ad4 = ((const float4*)att_dst)[tx];
    #pragma unroll
    for (int i = 0; i < 4; i++) {
        float pa = acc[i][0] * as4.x + acc[i][1] * as4.y + acc[i][2] * as4.z + acc[i][3] * as4.w;
        float pd = acc[i][0] * ad4.x + acc[i][1] * ad4.y + acc[i][2] * ad4.z + acc[i][3] * ad4.w;
        #pragma unroll
        for (int off = 8; off; off >>= 1) {
            pa += __shfl_down_sync(0xffffffffu, pa, off, 16);
            pd += __shfl_down_sync(0xffffffffu, pd, off, 16);
        }
        if (tx == 0) {
            int r = row0 + ty * 4 + i;
            if (r < N) { g_asrc[r] = pa; g_adst[r] = pd; }
        }
    }

    #pragma unroll
    for (int i = 0; i < 4; i++) {
        int r = row0 + ty * 4 + i;
        if (r >= N) continue;
        union { __half2 h[2]; float2 f; } u;
        u.h[0] = __floats2half2_rn(acc[i][0], acc[i][1]);
        u.h[1] = __floats2half2_rn(acc[i][2], acc[i][3]);
        ((float2*)g_h2)[r * 16 + tx] = u.f;
    }
}

// ---------------------------------------------------------------------------
// Kernel 2: single-pass exclusive scan of g_deg -> g_cursor (decoupled lookback)
// ---------------------------------------------------------------------------
#define FLAG_AGG  (1ull << 32)
#define FLAG_INCL (2ull << 32)

__global__ void scan_kernel(int N) {
    int t = threadIdx.x;
    int bid = blockIdx.x;
    int g = bid * 256 + t;
    int lane = t & 31, w = t >> 5;
    int v = (g < N) ? g_deg[g] : 0;
    int incl = v;
    #pragma unroll
    for (int off = 1; off < 32; off <<= 1) {
        int nv = __shfl_up_sync(0xffffffffu, incl, off);
        if (lane >= off) incl += nv;
    }
    __shared__ int wsum[8];
    if (lane == 31) wsum[w] = incl;
    __syncthreads();
    if (t < 8) {
        int xw = wsum[t];
        int in2 = xw;
        #pragma unroll
        for (int off = 1; off < 8; off <<= 1) {
            int nv = __shfl_up_sync(0xffu, in2, off);
            if (t >= off) in2 += nv;
        }
        wsum[t] = in2 - xw;   // exclusive warp offsets
    }
    __syncthreads();
    int excl = incl - v + wsum[w];

    __shared__ int sPrefix;
    __shared__ int sTotal;
    if (t == 255) sTotal = excl + v;
    __syncthreads();
    if (t == 0) {
        unsigned long long total = (unsigned long long)(unsigned)sTotal;
        if (bid == 0) {
            atomicExch(&g_pkt[0], total | FLAG_INCL);
            sPrefix = 0;
        } else {
            atomicExch(&g_pkt[bid], total | FLAG_AGG);
            long long run = 0;
            int j = bid - 1;
            while (true) {
                unsigned long long p;
                do { p = atomicAdd(&g_pkt[j], 0ull); } while ((p >> 32) == 0);
                run += (unsigned)(p & 0xffffffffu);
                if (p & FLAG_INCL) break;
                j--;
            }
            atomicExch(&g_pkt[bid], (total + (unsigned long long)(unsigned)run) | FLAG_INCL);
            sPrefix = (int)run;
        }
    }
    __syncthreads();
    if (g < N) g_cursor[g] = excl + sPrefix;
}

// ---------------------------------------------------------------------------
// Kernel 3: scatter edges into CSR (src AND dst per slot); re-zero g_pkt.
// ---------------------------------------------------------------------------
__global__ void scatter_kernel(const int* __restrict__ ei, int E) {
    int i = blockIdx.x * blockDim.x + threadIdx.x;
    if (i < SCAN_BLOCKS) g_pkt[i] = 0ull;
    if (i >= E) return;
    int s = ei[i];
    int d = ei[E + i];
    int pos = atomicAdd(&g_cursor[d], 1);
    g_csrc[pos] = s;
    g_cdst[pos] = d;
}

// ---------------------------------------------------------------------------
// Kernel 4: edge-parallel partials. 16 lanes per CSR slot, 32 slots per block.
// dst-sorted slots -> in-block segmented reduction over equal-dst runs; only
// run HEADS issue red.v4 into g_agg and one atomicAdd into g_denom.
// Per thread: O(1) loads; parallelism = 25.6M threads (throughput-bound).
// ---------------------------------------------------------------------------
__global__ __launch_bounds__(512) void edge_kernel(int E) {
    __shared__ int   sd[32];
    __shared__ float se[32];
    __shared__ float sval[32 * 64];
    int t = threadIdx.x;
    int grp = t >> 4, l16 = t & 15;
    int p = blockIdx.x * 32 + grp;
    bool valid = p < E;

    int s = 0, d = -1;
    float e = 0.f;
    float4 val = make_float4(0.f, 0.f, 0.f, 0.f);
    if (valid) {
        s = __ldg(g_csrc + p);
        d = __ldg(g_cdst + p);
        if (l16 == 0) e = __expf(lrelu(__ldg(g_asrc + s) + __ldg(g_adst + d)));
    }
    e = __shfl_sync(0xffffffffu, e, 0, 16);   // broadcast within the 16-lane group
    if (valid) {
        float2 pck = __ldg((const float2*)g_h2 + s * 16 + l16);
        float2 lo = __half22float2(((const __half2*)&pck)[0]);
        float2 hi = __half22float2(((const __half2*)&pck)[1]);
        val = make_float4(lo.x * e, lo.y * e, hi.x * e, hi.y * e);
    }
    if (l16 == 0) { sd[grp] = d; se[grp] = e; }
    *(float4*)&sval[grp * 64 + l16 * 4] = val;
    __syncthreads();

    bool head = valid && (grp == 0 || sd[grp - 1] != d);
    if (head) {
        float4 sum = val;
        float esum = e;
        for (int j = grp + 1; j < 32 && sd[j] == d; j++) {
            float4 v2 = *(float4*)&sval[j * 64 + l16 * 4];
            sum.x += v2.x; sum.y += v2.y; sum.z += v2.z; sum.w += v2.w;
            esum += se[j];
        }
        float* dst = g_agg + (size_t)d * 64 + l16 * 4;
        asm volatile("red.global.add.v4.f32 [%0], {%1,%2,%3,%4};"
                     :: "l"(dst), "f"(sum.x), "f"(sum.y), "f"(sum.z), "f"(sum.w)
                     : "memory");
        if (l16 == 0) atomicAdd(&g_denom[d], esum);
    }
}

// ---------------------------------------------------------------------------
// Kernel 5: streaming finish. Per node: add self-loop term, normalize, +bias,
// relu, accumulate column sums; spread-RED block partials; last block does the
// 64x64 matvec and re-zeroes all replay state (g_deg/g_smulti/g_done).
// ---------------------------------------------------------------------------
__global__ void finish_kernel(const float* __restrict__ bias,
                              const float* __restrict__ W_lin, const float* __restrict__ b_lin,
                              float* __restrict__ out, float invN, int N) {
    __shared__ float sm[64];
    __shared__ float sf[64];
    __shared__ int lastFlag;
    int t = threadIdx.x;
    if (t < 64) sm[t] = 0.f;
    __syncthreads();

    int grp = t >> 4, l16 = t & 15;
    float4 bv = ((const float4*)bias)[l16];
    float4 accS = make_float4(0.f, 0.f, 0.f, 0.f);

    for (int base = blockIdx.x * 16; base < N; base += gridDim.x * 16) {
        int n = base + grp;
        bool act = n < N;
        float asn = 0.f, adn = 0.f, dn = 0.f;
        if (act && l16 == 0) {
            asn = __ldg(g_asrc + n);
            adn = __ldg(g_adst + n);
            dn  = g_denom[n];
            g_deg[n] = 0;                  // cleanup for next replay's histogram
        }
        float es = __expf(lrelu(asn + adn));
        es = __shfl_sync(0xffffffffu, es, 0, 16);
        dn = __shfl_sync(0xffffffffu, dn, 0, 16);
        if (act) {
            float inv = 1.f / (dn + es);
            float4 a = ((const float4*)g_agg)[n * 16 + l16];
            float2 pck = __ldg((const float2*)g_h2 + n * 16 + l16);
            float2 lo = __half22float2(((const __half2*)&pck)[0]);
            float2 hi = __half22float2(((const __half2*)&pck)[1]);
            accS.x += fmaxf((a.x + lo.x * es) * inv + bv.x, 0.f);
            accS.y += fmaxf((a.y + lo.y * es) * inv + bv.y, 0.f);
            accS.z += fmaxf((a.z + hi.x * es) * inv + bv.z, 0.f);
            accS.w += fmaxf((a.w + hi.y * es) * inv + bv.w, 0.f);
        }
    }
    atomicAdd(&sm[l16 * 4 + 0], accS.x);
    atomicAdd(&sm[l16 * 4 + 1], accS.y);
    atomicAdd(&sm[l16 * 4 + 2], accS.z);
    atomicAdd(&sm[l16 * 4 + 3], accS.w);
    __syncthreads();

    if (t < 16) {
        float4 v = *(float4*)&sm[t * 4];
        float* dst = g_smulti + (blockIdx.x & 63) * 64 + t * 4;   // 64-way spread
        asm volatile("red.global.add.v4.f32 [%0], {%1,%2,%3,%4};"
                     :: "l"(dst), "f"(v.x), "f"(v.y), "f"(v.z), "f"(v.w)
                     : "memory");
        __threadfence();
    }
    __syncthreads();
    if (t == 0) {
        int old = atomicAdd(&g_done, 1);
        lastFlag = (old == (int)gridDim.x - 1);
    }
    __syncthreads();

    if (lastFlag) {
        __threadfence();   // acquire: all blocks' reds visible
        if (t < 64) {
            float v = 0.f;
            #pragma unroll 8
            for (int j = 0; j < 64; j++) {
                float pj;
                asm volatile("ld.global.cg.f32 %0, [%1];" : "=f"(pj) : "l"(g_smulti + j * 64 + t));
                v += pj;
                g_smulti[j * 64 + t] = 0.f;   // cleanup for next replay
            }
            sf[t] = v;
        }
        __syncthreads();
        if (t < 64) {
            float acc2 = b_lin[t];
            #pragma unroll 8
            for (int c = 0; c < 64; c++)
                acc2 += (sf[c] * invN) * W_lin[c * 64 + t];
            out[t] = acc2;
        }
        if (t == 0) g_done = 0;               // cleanup for next replay
    }
}

// ---------------------------------------------------------------------------
extern "C" void kernel_launch(void* const* d_in, const int* in_sizes, int n_in,
                              void* d_out, int out_size) {
    const float* x       = (const float*)d_in[0];
    const int*   ei      = (const int*)d_in[1];
    const float* W       = (const float*)d_in[2];
    const float* att_src = (const float*)d_in[3];
    const float* att_dst = (const float*)d_in[4];
    const float* bias    = (const float*)d_in[5];
    const float* W_lin   = (const float*)d_in[6];
    const float* b_lin   = (const float*)d_in[7];

    int N = in_sizes[0] / 128;   // 100000
    int E = in_sizes[1] / 2;     // 1600000
    int GB = (N + 63) / 64;      // gemm blocks
    int HB = (E + 255) / 256;    // hist blocks
    int ZB = (N * 16 + N / 4 + 255) / 256;   // zero blocks (g_agg + g_denom in float4)

    gemm_hist_zero_kernel<<<GB + HB + ZB, 256>>>(x, W, att_src, att_dst, ei, N, E, GB, HB);
    scan_kernel<<<(N + 255) / 256, 256>>>(N);
    scatter_kernel<<<(E + 255) / 256, 256>>>(ei, E);
    edge_kernel<<<(E + 31) / 32, 512>>>(E);
    finish_kernel<<<1184, 256>>>(bias, W_lin, b_lin, (float*)d_out, 1.0f / (float)N, N);
}

// round 12
// speedup vs baseline: 2.2333x; 1.6681x over previous
#include <cuda_runtime.h>
#include <cuda_fp16.h>

// ---------------------------------------------------------------------------
// DummyGAT: h = x@W; GAT edge softmax + aggregation; out = mean(relu(agg)@W_lin + b_lin)
// N = 100000 nodes, E = 1.6M edges, IN=128, HID=64, OUT=64
// 5 launches: [gemm+hist+zero] -> [scan] -> [scatter] -> [edge partials] -> [finish]
// Edge pass: 16-lane group per 4 consecutive dst-sorted slots, in-group run
// dedup, no smem / no syncthreads / no serial scans.
// ---------------------------------------------------------------------------

#define N_MAX 100000
#define E_MAX 1600000
#define SCAN_BLOCKS 391   // ceil(100000/256)

__device__ __align__(256) __half g_h2[N_MAX * 64];    // h in fp16 (gather operand)
__device__ __align__(256) float  g_asrc[N_MAX];
__device__ __align__(256) float  g_adst[N_MAX];
__device__ __align__(256) float  g_agg[N_MAX * 64];   // edge-sum accumulator (zeroed in K1)
__device__ __align__(256) float  g_denom[N_MAX];      // edge exp-sum (zeroed in K1)
__device__ __align__(256) int    g_deg[N_MAX];        // in-degree (zeroed by finish)
__device__ __align__(256) int    g_cursor[N_MAX];     // scan result / scatter cursor
__device__ __align__(256) int    g_csrc[E_MAX];       // CSR: src per (dst-sorted) slot
__device__ __align__(256) int    g_cdst[E_MAX];       // CSR: dst per slot
__device__ __align__(256) unsigned long long g_pkt[SCAN_BLOCKS]; // lookback, zeroed by scatter
__device__ __align__(256) float  g_smulti[64 * 64];   // spread node-sum slots (zeroed by finish)
__device__ int g_done;                                // zeroed by finish

__device__ __forceinline__ float lrelu(float x) { return x > 0.f ? x : 0.2f * x; }

// ---------------------------------------------------------------------------
// Kernel 1: three block partitions.
//  [0,GB): h = x@W + attention scores (k-major x tile -> FFMA-bound)
//  [GB,GB+HB): in-degree histogram
//  [GB+HB,..): zero g_agg and g_denom (float4 streams, hidden under gemm)
// ---------------------------------------------------------------------------
__global__ void gemm_hist_zero_kernel(const float* __restrict__ x, const float* __restrict__ W,
                                      const float* __restrict__ att_src, const float* __restrict__ att_dst,
                                      const int* __restrict__ ei, int N, int E, int GB, int HB) {
    if (blockIdx.x >= GB + HB) {          // ---- zero partition ----
        int i = (blockIdx.x - GB - HB) * 256 + threadIdx.x;
        int nAgg = N * 16;                // g_agg in float4 units
        if (i < nAgg) ((float4*)g_agg)[i] = make_float4(0.f, 0.f, 0.f, 0.f);
        else if (i - nAgg < N / 4) ((float4*)g_denom)[i - nAgg] = make_float4(0.f, 0.f, 0.f, 0.f);
        return;
    }
    if (blockIdx.x >= GB) {               // ---- histogram partition ----
        int i = (blockIdx.x - GB) * 256 + threadIdx.x;
        if (i < E) atomicAdd(&g_deg[ei[E + i]], 1);
        return;
    }
    // ---- gemm partition ----
    int row0 = blockIdx.x * 64;

    __shared__ float xs[64 * 68];    // k-major: xs[k*68 + r]
    __shared__ float ws[64 * 64];    // [k][c]
    int tx = threadIdx.x & 15;       // col group (4 cols)
    int ty = threadIdx.x >> 4;       // row group (4 rows)
    float acc[4][4] = {};

    for (int k0 = 0; k0 < 128; k0 += 64) {
        #pragma unroll
        for (int i = 0; i < 4; i++) {
            int idx = threadIdx.x + i * 256;
            int r = idx >> 4, c4 = idx & 15;
            int grow = row0 + r;
            float4 v = make_float4(0.f, 0.f, 0.f, 0.f);
            if (grow < N) v = ((const float4*)x)[grow * 32 + (k0 >> 2) + c4];
            int kk = c4 * 4;
            xs[(kk + 0) * 68 + r] = v.x;
            xs[(kk + 1) * 68 + r] = v.y;
            xs[(kk + 2) * 68 + r] = v.z;
            xs[(kk + 3) * 68 + r] = v.w;
        }
        #pragma unroll
        for (int i = 0; i < 4; i++) {
            int idx = threadIdx.x + i * 256;
            ((float4*)ws)[idx] = ((const float4*)(W + k0 * 64))[idx];
        }
        __syncthreads();

        #pragma unroll 16
        for (int k = 0; k < 64; k++) {
            float4 xv = *(float4*)&xs[k * 68 + ty * 4];   // broadcast: 2 addrs/warp
            float4 wv = *(float4*)&ws[k * 64 + tx * 4];
            acc[0][0] += xv.x * wv.x; acc[0][1] += xv.x * wv.y; acc[0][2] += xv.x * wv.z; acc[0][3] += xv.x * wv.w;
            acc[1][0] += xv.y * wv.x; acc[1][1] += xv.y * wv.y; acc[1][2] += xv.y * wv.z; acc[1][3] += xv.y * wv.w;
            acc[2][0] += xv.z * wv.x; acc[2][1] += xv.z * wv.y; acc[2][2] += xv.z * wv.z; acc[2][3] += xv.z * wv.w;
            acc[3][0] += xv.w * wv.x; acc[3][1] += xv.w * wv.y; acc[3][2] += xv.w * wv.z; acc[3][3] += xv.w * wv.w;
        }
        __syncthreads();
    }

    // attention scores via width-16 shuffle reduce
    float4 as4 = ((const float4*)att_src)[tx];
    float4 ad4 = ((const float4*)att_dst)[tx];
    #pragma unroll
    for (int i = 0; i < 4; i++) {
        float pa = acc[i][0] * as4.x + acc[i][1] * as4.y + acc[i][2] * as4.z + acc[i][3] * as4.w;
        float pd = acc[i][0] * ad4.x + acc[i][1] * ad4.y + acc[i][2] * ad4.z + acc[i][3] * ad4.w;
        #pragma unroll
        for (int off = 8; off; off >>= 1) {
            pa += __shfl_down_sync(0xffffffffu, pa, off, 16);
            pd += __shfl_down_sync(0xffffffffu, pd, off, 16);
        }
        if (tx == 0) {
            int r = row0 + ty * 4 + i;
            if (r < N) { g_asrc[r] = pa; g_adst[r] = pd; }
        }
    }

    #pragma unroll
    for (int i = 0; i < 4; i++) {
        int r = row0 + ty * 4 + i;
        if (r >= N) continue;
        union { __half2 h[2]; float2 f; } u;
        u.h[0] = __floats2half2_rn(acc[i][0], acc[i][1]);
        u.h[1] = __floats2half2_rn(acc[i][2], acc[i][3]);
        ((float2*)g_h2)[r * 16 + tx] = u.f;
    }
}

// ---------------------------------------------------------------------------
// Kernel 2: single-pass exclusive scan of g_deg -> g_cursor (decoupled lookback)
// ---------------------------------------------------------------------------
#define FLAG_AGG  (1ull << 32)
#define FLAG_INCL (2ull << 32)

__global__ void scan_kernel(int N) {
    int t = threadIdx.x;
    int bid = blockIdx.x;
    int g = bid * 256 + t;
    int lane = t & 31, w = t >> 5;
    int v = (g < N) ? g_deg[g] : 0;
    int incl = v;
    #pragma unroll
    for (int off = 1; off < 32; off <<= 1) {
        int nv = __shfl_up_sync(0xffffffffu, incl, off);
        if (lane >= off) incl += nv;
    }
    __shared__ int wsum[8];
    if (lane == 31) wsum[w] = incl;
    __syncthreads();
    if (t < 8) {
        int xw = wsum[t];
        int in2 = xw;
        #pragma unroll
        for (int off = 1; off < 8; off <<= 1) {
            int nv = __shfl_up_sync(0xffu, in2, off);
            if (t >= off) in2 += nv;
        }
        wsum[t] = in2 - xw;   // exclusive warp offsets
    }
    __syncthreads();
    int excl = incl - v + wsum[w];

    __shared__ int sPrefix;
    __shared__ int sTotal;
    if (t == 255) sTotal = excl + v;
    __syncthreads();
    if (t == 0) {
        unsigned long long total = (unsigned long long)(unsigned)sTotal;
        if (bid == 0) {
            atomicExch(&g_pkt[0], total | FLAG_INCL);
            sPrefix = 0;
        } else {
            atomicExch(&g_pkt[bid], total | FLAG_AGG);
            long long run = 0;
            int j = bid - 1;
            while (true) {
                unsigned long long p;
                do { p = atomicAdd(&g_pkt[j], 0ull); } while ((p >> 32) == 0);
                run += (unsigned)(p & 0xffffffffu);
                if (p & FLAG_INCL) break;
                j--;
            }
            atomicExch(&g_pkt[bid], (total + (unsigned long long)(unsigned)run) | FLAG_INCL);
            sPrefix = (int)run;
        }
    }
    __syncthreads();
    if (g < N) g_cursor[g] = excl + sPrefix;
}

// ---------------------------------------------------------------------------
// Kernel 3: scatter edges into CSR (src AND dst per slot); re-zero g_pkt.
// ---------------------------------------------------------------------------
__global__ void scatter_kernel(const int* __restrict__ ei, int E) {
    int i = blockIdx.x * blockDim.x + threadIdx.x;
    if (i < SCAN_BLOCKS) g_pkt[i] = 0ull;
    if (i >= E) return;
    int s = ei[i];
    int d = ei[E + i];
    int pos = atomicAdd(&g_cursor[d], 1);
    g_csrc[pos] = s;
    g_cdst[pos] = d;
}

// ---------------------------------------------------------------------------
// Kernel 4: edge-parallel partials, no smem / no syncthreads.
// Each 16-lane group owns 4 CONSECUTIVE dst-sorted slots: broadcast index
// loads, 4 independent h-row loads (MLP 8/warp), in-group run merge, flush =
// red.v4 (+ scalar denom atomic) per run. ~1.2 flushes per group expected.
// ---------------------------------------------------------------------------
__device__ __forceinline__ void flush_run(int d, float4 acc, float ea, int l16) {
    float* dst = g_agg + (size_t)d * 64 + l16 * 4;
    asm volatile("red.global.add.v4.f32 [%0], {%1,%2,%3,%4};"
                 :: "l"(dst), "f"(acc.x), "f"(acc.y), "f"(acc.z), "f"(acc.w)
                 : "memory");
    if (l16 == 0) atomicAdd(&g_denom[d], ea);
}

__global__ __launch_bounds__(512) void edge_kernel(int E) {
    int t = threadIdx.x;
    int grp = t >> 4, l16 = t & 15;
    int base = (blockIdx.x * 32 + grp) * 4;
    if (base >= E) return;
    int rem = E - base;                      // >= 1

    int   s[4], d[4];
    float e[4];
    #pragma unroll
    for (int i = 0; i < 4; i++) {
        bool v = i < rem;
        s[i] = v ? __ldg(g_csrc + base + i) : 0;
        d[i] = v ? __ldg(g_cdst + base + i) : 0;
    }
    #pragma unroll
    for (int i = 0; i < 4; i++) {
        bool v = i < rem;
        e[i] = v ? __expf(lrelu(__ldg(g_asrc + s[i]) + __ldg(g_adst + d[i]))) : 0.f;
    }
    #pragma unroll
    for (int i = 1; i < 4; i++)              // invalid slots merge into prior run (add 0)
        if (i >= rem) d[i] = d[i - 1];

    float4 val[4];
    #pragma unroll
    for (int i = 0; i < 4; i++) {
        if (i < rem) {
            float2 p = __ldg((const float2*)g_h2 + s[i] * 16 + l16);
            float2 lo = __half22float2(((const __half2*)&p)[0]);
            float2 hi = __half22float2(((const __half2*)&p)[1]);
            val[i] = make_float4(lo.x * e[i], lo.y * e[i], hi.x * e[i], hi.y * e[i]);
        } else {
            val[i] = make_float4(0.f, 0.f, 0.f, 0.f);
        }
    }

    // in-group run merge (branches are uniform across the 16-lane group)
    float4 acc = val[0];
    float  ea  = e[0];
    int    dc  = d[0];
    #pragma unroll
    for (int i = 1; i < 4; i++) {
        if (d[i] == dc) {
            acc.x += val[i].x; acc.y += val[i].y; acc.z += val[i].z; acc.w += val[i].w;
            ea += e[i];
        } else {
            flush_run(dc, acc, ea, l16);
            dc = d[i]; acc = val[i]; ea = e[i];
        }
    }
    flush_run(dc, acc, ea, l16);
}

// ---------------------------------------------------------------------------
// Kernel 5: streaming finish. Per node: add self-loop term, normalize, +bias,
// relu, accumulate column sums; spread-RED block partials; last block does the
// 64x64 matvec and re-zeroes all replay state (g_deg/g_smulti/g_done).
// ---------------------------------------------------------------------------
__global__ void finish_kernel(const float* __restrict__ bias,
                              const float* __restrict__ W_lin, const float* __restrict__ b_lin,
                              float* __restrict__ out, float invN, int N) {
    __shared__ float sm[64];
    __shared__ float sf[64];
    __shared__ int lastFlag;
    int t = threadIdx.x;
    if (t < 64) sm[t] = 0.f;
    __syncthreads();

    int grp = t >> 4, l16 = t & 15;
    float4 bv = ((const float4*)bias)[l16];
    float4 accS = make_float4(0.f, 0.f, 0.f, 0.f);

    for (int base = blockIdx.x * 16; base < N; base += gridDim.x * 16) {
        int n = base + grp;
        bool act = n < N;
        float asn = 0.f, adn = 0.f, dn = 0.f;
        if (act && l16 == 0) {
            asn = __ldg(g_asrc + n);
            adn = __ldg(g_adst + n);
            dn  = g_denom[n];
            g_deg[n] = 0;                  // cleanup for next replay's histogram
        }
        float es = __expf(lrelu(asn + adn));
        es = __shfl_sync(0xffffffffu, es, 0, 16);
        dn = __shfl_sync(0xffffffffu, dn, 0, 16);
        if (act) {
            float inv = 1.f / (dn + es);
            float4 a = ((const float4*)g_agg)[n * 16 + l16];
            float2 pck = __ldg((const float2*)g_h2 + n * 16 + l16);
            float2 lo = __half22float2(((const __half2*)&pck)[0]);
            float2 hi = __half22float2(((const __half2*)&pck)[1]);
            accS.x += fmaxf((a.x + lo.x * es) * inv + bv.x, 0.f);
            accS.y += fmaxf((a.y + lo.y * es) * inv + bv.y, 0.f);
            accS.z += fmaxf((a.z + hi.x * es) * inv + bv.z, 0.f);
            accS.w += fmaxf((a.w + hi.y * es) * inv + bv.w, 0.f);
        }
    }
    atomicAdd(&sm[l16 * 4 + 0], accS.x);
    atomicAdd(&sm[l16 * 4 + 1], accS.y);
    atomicAdd(&sm[l16 * 4 + 2], accS.z);
    atomicAdd(&sm[l16 * 4 + 3], accS.w);
    __syncthreads();

    if (t < 16) {
        float4 v = *(float4*)&sm[t * 4];
        float* dst = g_smulti + (blockIdx.x & 63) * 64 + t * 4;   // 64-way spread
        asm volatile("red.global.add.v4.f32 [%0], {%1,%2,%3,%4};"
                     :: "l"(dst), "f"(v.x), "f"(v.y), "f"(v.z), "f"(v.w)
                     : "memory");
        __threadfence();
    }
    __syncthreads();
    if (t == 0) {
        int old = atomicAdd(&g_done, 1);
        lastFlag = (old == (int)gridDim.x - 1);
    }
    __syncthreads();

    if (lastFlag) {
        __threadfence();   // acquire: all blocks' reds visible
        if (t < 64) {
            float v = 0.f;
            #pragma unroll 8
            for (int j = 0; j < 64; j++) {
                float pj;
                asm volatile("ld.global.cg.f32 %0, [%1];" : "=f"(pj) : "l"(g_smulti + j * 64 + t));
                v += pj;
                g_smulti[j * 64 + t] = 0.f;   // cleanup for next replay
            }
            sf[t] = v;
        }
        __syncthreads();
        if (t < 64) {
            float acc2 = b_lin[t];
            #pragma unroll 8
            for (int c = 0; c < 64; c++)
                acc2 += (sf[c] * invN) * W_lin[c * 64 + t];
            out[t] = acc2;
        }
        if (t == 0) g_done = 0;               // cleanup for next replay
    }
}

// ---------------------------------------------------------------------------
extern "C" void kernel_launch(void* const* d_in, const int* in_sizes, int n_in,
                              void* d_out, int out_size) {
    const float* x       = (const float*)d_in[0];
    const int*   ei      = (const int*)d_in[1];
    const float* W       = (const float*)d_in[2];
    const float* att_src = (const float*)d_in[3];
    const float* att_dst = (const float*)d_in[4];
    const float* bias    = (const float*)d_in[5];
    const float* W_lin   = (const float*)d_in[6];
    const float* b_lin   = (const float*)d_in[7];

    int N = in_sizes[0] / 128;   // 100000
    int E = in_sizes[1] / 2;     // 1600000
    int GB = (N + 63) / 64;      // gemm blocks
    int HB = (E + 255) / 256;    // hist blocks
    int ZB = (N * 16 + N / 4 + 255) / 256;   // zero blocks (g_agg + g_denom in float4)

    gemm_hist_zero_kernel<<<GB + HB + ZB, 256>>>(x, W, att_src, att_dst, ei, N, E, GB, HB);
    scan_kernel<<<(N + 255) / 256, 256>>>(N);
    scatter_kernel<<<(E + 255) / 256, 256>>>(ei, E);
    edge_kernel<<<(E + 127) / 128, 512>>>(E);
    finish_kernel<<<1184, 256>>>(bias, W_lin, b_lin, (float*)d_out, 1.0f / (float)N, N);
}